// round 12
// baseline (speedup 1.0000x reference)
#include <cuda_runtime.h>
#include <math.h>
#include <stdint.h>

#define NB 64
#define NS 4096
#define ND 256
#define SPLIT 8
#define CHUNK (NS / SPLIT)            // 512 rows per CTA
#define NCW 8                         // consumer warps
#define BLOCK (32 * (NCW + 1))        // 288: 8 consumer + 1 producer warp
#define TILE_ROWS 16
#define NTILES (CHUNK / TILE_ROWS)    // 32 tiles per CTA
#define TILE_BYTES (TILE_ROWS * ND * 4)   // 16384
#define DEPTH 3                       // ring depth (48 KB)
#define RPWT (TILE_ROWS / NCW)        // 2 rows per consumer warp per tile

// smem layout (dynamic)
#define SM_BUF    0
#define SM_FULL   (DEPTH * TILE_BYTES)                // 49152
#define SM_EMPTY  (SM_FULL + DEPTH * 8)
#define SM_ACC    (((SM_EMPTY + DEPTH * 8) + 15) & ~15)
#define SM_DEN    (SM_ACC + 4 * ND * 4)               // s_acc: 4 rows only
#define SM_RED    (SM_DEN + NCW * 4)
#define SM_FLAG   (SM_RED + 4 * 4)
#define SM_TOTAL  (SM_FLAG + 16)                      // ~53.4 KB -> 4 CTAs/SM

__device__ float g_num[NB * SPLIT * ND];
__device__ float g_den[NB * SPLIT];
__device__ unsigned int g_cnt[NB];    // zero-init; winning CTA resets

__device__ __forceinline__ float tanh_fast(float x) {
    float e = __expf(2.0f * x);
    return 1.0f - __fdividef(2.0f, e + 1.0f);
}

__device__ __forceinline__ void mbar_init(uint32_t mbar, uint32_t count) {
    asm volatile("mbarrier.init.shared.b64 [%0], %1;" :: "r"(mbar), "r"(count) : "memory");
}
__device__ __forceinline__ void mbar_expect_tx(uint32_t mbar, uint32_t bytes) {
    asm volatile("mbarrier.arrive.expect_tx.shared.b64 _, [%0], %1;"
                 :: "r"(mbar), "r"(bytes) : "memory");
}
__device__ __forceinline__ void mbar_arrive(uint32_t mbar) {
    asm volatile("mbarrier.arrive.release.cta.shared::cta.b64 _, [%0];"
                 :: "r"(mbar) : "memory");
}
__device__ __forceinline__ void bulk_cp(uint32_t dst, const void* src, uint32_t mbar) {
    asm volatile("cp.async.bulk.shared::cta.global.mbarrier::complete_tx::bytes "
                 "[%0], [%1], %2, [%3];"
                 :: "r"(dst), "l"(src), "r"((uint32_t)TILE_BYTES), "r"(mbar) : "memory");
}
__device__ __forceinline__ void mbar_wait(uint32_t mbar, uint32_t parity) {
    uint32_t done;
    asm volatile("{\n\t.reg .pred p;\n\t"
                 "mbarrier.try_wait.parity.acquire.cta.shared::cta.b64 p, [%1], %2;\n\t"
                 "selp.b32 %0, 1, 0, p;\n\t}"
                 : "=r"(done) : "r"(mbar), "r"(parity) : "memory");
    if (!done) {
        asm volatile("{\n\t.reg .pred P1;\n\t"
                     "W_%=:\n\t"
                     "mbarrier.try_wait.parity.acquire.cta.shared::cta.b64 P1, [%0], %1, 0x989680;\n\t"
                     "@P1 bra.uni D_%=;\n\t"
                     "bra.uni W_%=;\n\t"
                     "D_%=:\n\t}"
                     :: "r"(mbar), "r"(parity) : "memory");
    }
}

__global__ __launch_bounds__(BLOCK)
void att_fused(const float* __restrict__ aspect,
               const float* __restrict__ memory,
               const float* __restrict__ W,
               const float* __restrict__ bias,
               float* __restrict__ out)
{
    extern __shared__ char smem[];
    float* sbuf   = (float*)(smem + SM_BUF);
    float* s_acc  = (float*)(smem + SM_ACC);     // [4][ND]
    float* s_den  = (float*)(smem + SM_DEN);     // [NCW]
    float* s_red  = (float*)(smem + SM_RED);     // [4]
    int*   s_flag = (int*)  (smem + SM_FLAG);
    const uint32_t smem_u32 = (uint32_t)__cvta_generic_to_shared(smem);
    const uint32_t full0  = smem_u32 + SM_FULL;
    const uint32_t empty0 = smem_u32 + SM_EMPTY;

    const int b     = blockIdx.y;
    const int chunk = blockIdx.x;
    const int tid   = threadIdx.x;
    const int warp  = tid >> 5;
    const int lane  = tid & 31;

    const float* memb = memory + ((size_t)b * NS + (size_t)chunk * CHUNK) * ND;

    if (tid == 0) {
        #pragma unroll
        for (int s = 0; s < DEPTH; s++) {
            mbar_init(full0  + s * 8, 1);    // producer's expect_tx arrive
            mbar_init(empty0 + s * 8, NCW);  // one arrive per consumer warp
        }
        asm volatile("fence.proxy.async.shared::cta;" ::: "memory");
    }

    // a_b = aspect[b].Wa + bias  (first 4 warps; ordered by the syncthreads)
    if (tid < 128) {
        float av = aspect[b * ND + tid]       * W[ND + tid]
                 + aspect[b * ND + tid + 128] * W[ND + tid + 128];
        #pragma unroll
        for (int o = 16; o; o >>= 1) av += __shfl_xor_sync(0xFFFFFFFFu, av, o);
        if (lane == 0) s_red[warp] = av;
    }
    __syncthreads();   // orders mbar inits + s_red for everyone
    const float a_b = bias[0] + s_red[0] + s_red[1] + s_red[2] + s_red[3];

    float acc[8] = {0.f,0.f,0.f,0.f,0.f,0.f,0.f,0.f};
    float den = 0.f;

    // ───────── producer warp ─────────
    if (warp == NCW) {
        if (lane == 0) {
            int slot = 0; uint32_t phase = 1;   // first DEPTH empty-waits pass
            #pragma unroll 1
            for (int t = 0; t < NTILES; t++) {
                mbar_wait(empty0 + slot * 8, phase);
                mbar_expect_tx(full0 + slot * 8, TILE_BYTES);
                bulk_cp(smem_u32 + SM_BUF + slot * TILE_BYTES,
                        memb + (size_t)t * TILE_ROWS * ND, full0 + slot * 8);
                if (++slot == DEPTH) { slot = 0; phase ^= 1; }
            }
        }
    } else {
        // ───────── consumer warps: warp w owns rows [2w, 2w+2) of each tile ─────
        float w[8];                                  // lane owns dims {lane+32k}
        #pragma unroll
        for (int k = 0; k < 8; k++) w[k] = W[lane + 32 * k];

        int slot = 0; uint32_t phase = 0;
        #pragma unroll 1
        for (int t = 0; t < NTILES; t++) {
            mbar_wait(full0 + slot * 8, phase);

            const float* srow = sbuf + slot * (TILE_ROWS * ND) + (warp * RPWT) * ND + lane;
            float m[RPWT][8];
            #pragma unroll
            for (int r = 0; r < RPWT; r++)
                #pragma unroll
                for (int k = 0; k < 8; k++)
                    m[r][k] = srow[r * ND + 32 * k];

            // dot: consumes every loaded value -> slot fully read after this
            float d[RPWT];
            #pragma unroll
            for (int r = 0; r < RPWT; r++) {
                float s = m[r][0] * w[0];
                #pragma unroll
                for (int k = 1; k < 8; k++) s = fmaf(m[r][k], w[k], s);
                d[r] = s;
            }

            // release slot for refill before the compute tail
            if (lane == 0) mbar_arrive(empty0 + slot * 8);

            #pragma unroll
            for (int o = 16; o; o >>= 1) {
                #pragma unroll
                for (int r = 0; r < RPWT; r++)
                    d[r] += __shfl_xor_sync(0xFFFFFFFFu, d[r], o);
            }
            #pragma unroll
            for (int r = 0; r < RPWT; r++) {
                const float gi = tanh_fast(d[r] + a_b);
                const float g  = __expf(gi - 1.0f);   // gi in [-1,1]: fixed max=1
                den += g;
                #pragma unroll
                for (int k = 0; k < 8; k++) acc[k] = fmaf(g, m[r][k], acc[k]);
            }

            if (++slot == DEPTH) { slot = 0; phase ^= 1; }
        }
        if (lane == 0) s_den[warp] = den;
    }

    // Two-step warp combine (keeps s_acc at 4 KB): warps 4-7 write, 0-3 add.
    if (warp >= 4 && warp < NCW) {
        #pragma unroll
        for (int k = 0; k < 8; k++) s_acc[(warp - 4) * ND + lane + 32 * k] = acc[k];
    }
    __syncthreads();
    if (warp < 4) {
        #pragma unroll
        for (int k = 0; k < 8; k++) s_acc[warp * ND + lane + 32 * k] += acc[k];
    }
    __syncthreads();

    // per-CTA partial -> gmem (one dim per consumer thread)
    const int idx = b * SPLIT + chunk;
    if (tid < ND) {
        g_num[(size_t)idx * ND + tid] =
            s_acc[0 * ND + tid] + s_acc[1 * ND + tid] + s_acc[2 * ND + tid] + s_acc[3 * ND + tid];
    }
    if (tid == 0) {
        float v = 0.f;
        #pragma unroll
        for (int i = 0; i < NCW; i++) v += s_den[i];
        g_den[idx] = v;
    }

    // fused finisher: last CTA of this batch reduces SPLIT partials
    __threadfence();
    __syncthreads();
    if (tid == 0) {
        unsigned old = atomicAdd(&g_cnt[b], 1u);
        s_flag[0] = (old == SPLIT - 1) ? 1 : 0;
    }
    __syncthreads();
    if (s_flag[0]) {
        __threadfence();                 // acquire: other CTAs' partials visible
        if (tid == 0) g_cnt[b] = 0;      // reset for next graph replay
        if (tid < ND) {
            float num = 0.f, dsum = 0.f;
            #pragma unroll
            for (int i = 0; i < SPLIT; i++) {
                num  += g_num[(size_t)(b * SPLIT + i) * ND + tid];
                dsum += g_den[b * SPLIT + i];
            }
            out[b * ND + tid] = __fdividef(num, dsum);
        }
    }
}

extern "C" void kernel_launch(void* const* d_in, const int* in_sizes, int n_in,
                              void* d_out, int out_size)
{
    const float* aspect = (const float*)d_in[0];  // (64, 1, 256)
    const float* memory = (const float*)d_in[1];  // (64, 4096, 256)
    const float* W      = (const float*)d_in[2];  // (512, 1)
    const float* bias   = (const float*)d_in[3];  // (1,)
    float* out = (float*)d_out;                   // (64, 256)

    static bool attr_set = false;
    if (!attr_set) {
        cudaFuncSetAttribute(att_fused,
                             cudaFuncAttributeMaxDynamicSharedMemorySize, SM_TOTAL);
        attr_set = true;
    }

    dim3 grid(SPLIT, NB);                 // 512 CTAs, 4/SM -> single wave
    att_fused<<<grid, BLOCK, SM_TOTAL>>>(aspect, memory, W, bias, out);
}